// round 7
// baseline (speedup 1.0000x reference)
#include <cuda_runtime.h>
#include <cuda_bf16.h>

// char_feats: [L=512, B=256, D=256] f32 (time-major)
// word_ids:   [B, L] i32 (per-row non-decreasing, dense 0..n-1, < 128)
// attention_mask: [B, L] i32
// out: word_feats [W=128, B, D] f32 (+ masks [W, B] f32 if out_size allows)
#define LSEQ 512
#define NW   128
#define BATCH 256
#define DDIM  256
#define SPLIT_B 200

__device__ int g_start[BATCH * (NW + 1)];
__device__ int g_validhi[BATCH];
__device__ int g_wordnum[BATCH];
__device__ int g_ready[BATCH];   // zero-initialized at module load

__device__ __forceinline__ int clampw(int v) {
    return v < 0 ? 0 : (v > NW - 1 ? NW - 1 : v);
}

// Boundary metadata for batch row b, computed by one 64-thread block.
// Each thread owns 8 consecutive positions (2x int4 loads).
__device__ __forceinline__ void boundary_block(const int* __restrict__ word_ids,
                                               const int* __restrict__ amask,
                                               int b) {
    int t = threadIdx.x;           // 0..63
    int lane = t & 31;

    __shared__ int lastid[64];
    __shared__ int partial[2];

    const int4* wp = reinterpret_cast<const int4*>(word_ids + b * LSEQ);
    int4 w0 = wp[2 * t];
    int4 w1 = wp[2 * t + 1];
    int ids[8] = { clampw(w0.x), clampw(w0.y), clampw(w0.z), clampw(w0.w),
                   clampw(w1.x), clampw(w1.y), clampw(w1.z), clampw(w1.w) };

    const int4* mp = reinterpret_cast<const int4*>(amask + b * LSEQ);
    int4 m0 = mp[2 * t];
    int4 m1 = mp[2 * t + 1];
    int ms = m0.x + m0.y + m0.z + m0.w + m1.x + m1.y + m1.z + m1.w;
    #pragma unroll
    for (int s = 16; s > 0; s >>= 1) ms += __shfl_down_sync(0xffffffffu, ms, s);
    if (lane == 0) partial[t >> 5] = ms;

    lastid[t] = ids[7];

    // sentinel init for all 129 start slots
    int base = b * (NW + 1);
    g_start[base + t] = LSEQ;
    g_start[base + 64 + t] = LSEQ;
    if (t == 0) g_start[base + 128] = LSEQ;
    __syncthreads();

    int prev = (t == 0) ? -1 : lastid[t - 1];
    #pragma unroll
    for (int i = 0; i < 8; ++i) {
        if (ids[i] != prev) g_start[base + ids[i]] = 8 * t + i;
        prev = ids[i];
    }

    if (t == 63) g_wordnum[b] = ids[7] + 1;            // sorted -> last is max
    if (t == 0)  g_validhi[b] = (partial[0] + partial[1]) - 1;  // 1 + (sum-2)
    __syncthreads();

    if (t == 0) {
        __threadfence();
        ((volatile int*)g_ready)[b] = 1;
    }
}

template <bool STREAM>
__device__ __forceinline__ float4 ld_in(const float4* p) {
    return STREAM ? __ldcs(p) : __ldg(p);
}

// 4/2/1 ladder; single accumulator; fits the 32-reg budget.
template <bool STREAM>
__device__ __forceinline__ float4 pool_body(const float4* p, int stride4, int n) {
    float4 acc = make_float4(0.f, 0.f, 0.f, 0.f);
    int rem = n;
    while (rem >= 4) {
        float4 v0 = ld_in<STREAM>(p);
        float4 v1 = ld_in<STREAM>(p + stride4);
        float4 v2 = ld_in<STREAM>(p + 2 * stride4);
        float4 v3 = ld_in<STREAM>(p + 3 * stride4);
        acc.x += v0.x; acc.y += v0.y; acc.z += v0.z; acc.w += v0.w;
        acc.x += v1.x; acc.y += v1.y; acc.z += v1.z; acc.w += v1.w;
        acc.x += v2.x; acc.y += v2.y; acc.z += v2.z; acc.w += v2.w;
        acc.x += v3.x; acc.y += v3.y; acc.z += v3.z; acc.w += v3.w;
        p += 4 * stride4;
        rem -= 4;
    }
    if (rem >= 2) {
        float4 v0 = ld_in<STREAM>(p);
        float4 v1 = ld_in<STREAM>(p + stride4);
        acc.x += v0.x; acc.y += v0.y; acc.z += v0.z; acc.w += v0.w;
        acc.x += v1.x; acc.y += v1.y; acc.z += v1.z; acc.w += v1.w;
        p += 2 * stride4;
        rem -= 2;
    }
    if (rem >= 1) {
        float4 v0 = ld_in<STREAM>(p);
        acc.x += v0.x; acc.y += v0.y; acc.z += v0.z; acc.w += v0.w;
    }
    return acc;
}

// Fused kernel. 1D grid of NW*BATCH blocks, 64 threads each.
// Blocks 0..BATCH-1 additionally produce boundary metadata for batch = blockIdx.
// All blocks then pool (w = id & 127, b = id >> 7) after ready[b] is set.
__global__ void __launch_bounds__(64, 32)
fused_kernel(const float* __restrict__ cf,
             const int* __restrict__ word_ids,
             const int* __restrict__ amask,
             float* __restrict__ out,
             float* __restrict__ mask_out) {
    int lid = blockIdx.x;
    int t = threadIdx.x;

    if (lid < BATCH) {
        boundary_block(word_ids, amask, lid);
    }

    int w = lid & (NW - 1);
    int b = lid >> 7;

    // Wait for batch b's metadata (wave-1 always contains all producer blocks).
    if (t == 0) {
        while (((volatile int*)g_ready)[b] == 0) __nanosleep(64);
        __threadfence();   // acquire: order metadata loads after flag observation
    }
    __syncthreads();

    int base = b * (NW + 1);
    int s = g_start[base + w];
    int e = g_start[base + w + 1];
    int hi = g_validhi[b];

    s = s > 1 ? s : 1;
    e = e < hi ? e : hi;
    int n = e - s;

    const int stride4 = BATCH * DDIM / 4;
    const float4* p = reinterpret_cast<const float4*>(cf)
                    + (long long)s * stride4 + b * (DDIM / 4) + t;

    float4 acc = (b < SPLIT_B) ? pool_body<false>(p, stride4, n)
                               : pool_body<true>(p, stride4, n);

    float inv = 1.0f / (float)(n > 0 ? n : 1);
    acc.x *= inv; acc.y *= inv; acc.z *= inv; acc.w *= inv;

    float4* o = reinterpret_cast<float4*>(out)
              + (long long)(w * BATCH + b) * (DDIM / 4) + t;
    __stcs(o, acc);

    if (t == 0 && mask_out != nullptr) {
        __stcs(&mask_out[w * BATCH + b], (w < g_wordnum[b]) ? 1.0f : 0.0f);
    }
}

extern "C" void kernel_launch(void* const* d_in, const int* in_sizes, int n_in,
                              void* d_out, int out_size) {
    const float* char_feats = (const float*)d_in[0];
    const int*   word_ids   = (const int*)d_in[1];
    const int*   amask      = (const int*)d_in[2];
    float* out = (float*)d_out;

    const int feats_elems = NW * BATCH * DDIM;
    float* mask_out = (out_size > feats_elems) ? (out + feats_elems) : nullptr;

    fused_kernel<<<NW * BATCH, 64>>>(char_feats, word_ids, amask, out, mask_out);
}

// round 8
// speedup vs baseline: 1.0806x; 1.0806x over previous
#include <cuda_runtime.h>
#include <cuda_bf16.h>

// char_feats: [L=512, B=256, D=256] f32 (time-major)
// word_ids:   [B, L] i32 (per-row non-decreasing, dense 0..n-1, < 128)
// attention_mask: [B, L] i32
// out: word_feats [W=128, B, D] f32 (+ masks [W, B] f32 if out_size allows)
#define LSEQ 512
#define NW   128
#define BATCH 256
#define DDIM  256
#define SPLIT_B 200

__device__ __forceinline__ int clampw(int v) {
    return v < 0 ? 0 : (v > NW - 1 ? NW - 1 : v);
}

template <bool STREAM>
__device__ __forceinline__ float4 ld_in(const float4* p) {
    return STREAM ? __ldcs(p) : __ldg(p);
}

// 4/2/1 ladder; single accumulator; fits the 32-reg budget.
template <bool STREAM>
__device__ __forceinline__ float4 pool_body(const float4* p, int stride4, int n) {
    float4 acc = make_float4(0.f, 0.f, 0.f, 0.f);
    int rem = n;
    while (rem >= 4) {
        float4 v0 = ld_in<STREAM>(p);
        float4 v1 = ld_in<STREAM>(p + stride4);
        float4 v2 = ld_in<STREAM>(p + 2 * stride4);
        float4 v3 = ld_in<STREAM>(p + 3 * stride4);
        acc.x += v0.x; acc.y += v0.y; acc.z += v0.z; acc.w += v0.w;
        acc.x += v1.x; acc.y += v1.y; acc.z += v1.z; acc.w += v1.w;
        acc.x += v2.x; acc.y += v2.y; acc.z += v2.z; acc.w += v2.w;
        acc.x += v3.x; acc.y += v3.y; acc.z += v3.z; acc.w += v3.w;
        p += 4 * stride4;
        rem -= 4;
    }
    if (rem >= 2) {
        float4 v0 = ld_in<STREAM>(p);
        float4 v1 = ld_in<STREAM>(p + stride4);
        acc.x += v0.x; acc.y += v0.y; acc.z += v0.z; acc.w += v0.w;
        acc.x += v1.x; acc.y += v1.y; acc.z += v1.z; acc.w += v1.w;
        p += 2 * stride4;
        rem -= 2;
    }
    if (rem >= 1) {
        float4 v0 = ld_in<STREAM>(p);
        acc.x += v0.x; acc.y += v0.y; acc.z += v0.z; acc.w += v0.w;
    }
    return acc;
}

// Single fused kernel: one block per (word, batch); each block derives its own
// word range from the sorted word_ids row via counting — no inter-block sync.
// s = #(id <  w), e = #(id <= w), hi = sum(mask) - 1, wordnum = last_id + 1.
__global__ void __launch_bounds__(64, 32)
fused_kernel(const float* __restrict__ cf,
             const int* __restrict__ word_ids,
             const int* __restrict__ amask,
             float* __restrict__ out,
             float* __restrict__ mask_out) {
    int lid = blockIdx.x;
    int w = lid & (NW - 1);
    int b = lid >> 7;
    int t = threadIdx.x;  // 0..63

    __shared__ int ssum[2];
    __shared__ int slast;

    // --- metadata phase: 2KB word row + 2KB mask row, cooperative ---
    const int4* wp = reinterpret_cast<const int4*>(word_ids + b * LSEQ);
    int4 w0 = __ldg(wp + 2 * t);
    int4 w1 = __ldg(wp + 2 * t + 1);
    const int4* mp = reinterpret_cast<const int4*>(amask + b * LSEQ);
    int4 m0 = __ldg(mp + 2 * t);
    int4 m1 = __ldg(mp + 2 * t + 1);

    int ids[8] = { clampw(w0.x), clampw(w0.y), clampw(w0.z), clampw(w0.w),
                   clampw(w1.x), clampw(w1.y), clampw(w1.z), clampw(w1.w) };

    int cw = 0, ce = 0;
    #pragma unroll
    for (int i = 0; i < 8; ++i) {
        cw += (ids[i] < w);
        ce += (ids[i] <= w);
    }
    int msum = m0.x + m0.y + m0.z + m0.w + m1.x + m1.y + m1.z + m1.w;

    // pack three partial sums (each <= 512) into one int: 10|10|12 bits
    int packed = cw | (ce << 10) | (msum << 20);
    #pragma unroll
    for (int sft = 16; sft > 0; sft >>= 1)
        packed += __shfl_down_sync(0xffffffffu, packed, sft);
    if ((t & 31) == 0) ssum[t >> 5] = packed;
    if (t == 63) slast = ids[7];
    __syncthreads();

    int tot = ssum[0] + ssum[1];
    int s  = tot & 1023;
    int e  = (tot >> 10) & 1023;
    int hi = (tot >> 20) - 1;          // 1 + (sum(mask) - 2)
    int wordnum = slast + 1;           // sorted -> last id is max

    s = s > 1 ? s : 1;
    e = e < hi ? e : hi;
    int n = e - s;                     // may be <= 0 (empty / padded word)

    // --- pooling phase ---
    const int stride4 = BATCH * DDIM / 4;
    const float4* p = reinterpret_cast<const float4*>(cf)
                    + (long long)s * stride4 + b * (DDIM / 4) + t;

    float4 acc = (b < SPLIT_B) ? pool_body<false>(p, stride4, n)
                               : pool_body<true>(p, stride4, n);

    float inv = 1.0f / (float)(n > 0 ? n : 1);
    acc.x *= inv; acc.y *= inv; acc.z *= inv; acc.w *= inv;

    float4* o = reinterpret_cast<float4*>(out)
              + (long long)(w * BATCH + b) * (DDIM / 4) + t;
    __stcs(o, acc);

    if (t == 0 && mask_out != nullptr) {
        __stcs(&mask_out[w * BATCH + b], (w < wordnum) ? 1.0f : 0.0f);
    }
}

extern "C" void kernel_launch(void* const* d_in, const int* in_sizes, int n_in,
                              void* d_out, int out_size) {
    const float* char_feats = (const float*)d_in[0];
    const int*   word_ids   = (const int*)d_in[1];
    const int*   amask      = (const int*)d_in[2];
    float* out = (float*)d_out;

    const int feats_elems = NW * BATCH * DDIM;
    float* mask_out = (out_size > feats_elems) ? (out + feats_elems) : nullptr;

    fused_kernel<<<NW * BATCH, 64>>>(char_feats, word_ids, amask, out, mask_out);
}

// round 9
// speedup vs baseline: 1.2064x; 1.1164x over previous
#include <cuda_runtime.h>
#include <cuda_bf16.h>

// char_feats: [L=512, B=256, D=256] f32 (time-major)
// word_ids:   [B, L] i32 (per-row non-decreasing, dense 0..n-1, < 128)
// attention_mask: [B, L] i32
// out: word_feats [W=128, B, D] f32 (+ masks [W, B] f32 if out_size allows)
#define LSEQ 512
#define NW   128
#define BATCH 256
#define DDIM  256

__device__ __forceinline__ int clampw(int v) {
    return v < 0 ? 0 : (v > NW - 1 ? NW - 1 : v);
}

// 4/2/1 ladder; single accumulator; evict-first streaming loads.
__device__ __forceinline__ float4 pool_body(const float4* p, int stride4, int n) {
    float4 acc = make_float4(0.f, 0.f, 0.f, 0.f);
    int rem = n;
    while (rem >= 4) {
        float4 v0 = __ldcs(p);
        float4 v1 = __ldcs(p + stride4);
        float4 v2 = __ldcs(p + 2 * stride4);
        float4 v3 = __ldcs(p + 3 * stride4);
        acc.x += v0.x; acc.y += v0.y; acc.z += v0.z; acc.w += v0.w;
        acc.x += v1.x; acc.y += v1.y; acc.z += v1.z; acc.w += v1.w;
        acc.x += v2.x; acc.y += v2.y; acc.z += v2.z; acc.w += v2.w;
        acc.x += v3.x; acc.y += v3.y; acc.z += v3.z; acc.w += v3.w;
        p += 4 * stride4;
        rem -= 4;
    }
    if (rem >= 2) {
        float4 v0 = __ldcs(p);
        float4 v1 = __ldcs(p + stride4);
        acc.x += v0.x; acc.y += v0.y; acc.z += v0.z; acc.w += v0.w;
        acc.x += v1.x; acc.y += v1.y; acc.z += v1.z; acc.w += v1.w;
        p += 2 * stride4;
        rem -= 2;
    }
    if (rem >= 1) {
        float4 v0 = __ldcs(p);
        acc.x += v0.x; acc.y += v0.y; acc.z += v0.z; acc.w += v0.w;
    }
    return acc;
}

// One block per (word, batch); b is the FAST grid axis so concurrent CTAs
// read a contiguous sliding l-window of char_feats and store contiguous
// spans of out — DRAM row-buffer friendly.
// Block derives its word range locally from the sorted word_ids row:
// s = #(id < w), e = #(id <= w), hi = sum(mask) - 1, wordnum = last_id + 1.
__global__ void __launch_bounds__(64, 32)
fused_kernel(const float* __restrict__ cf,
             const int* __restrict__ word_ids,
             const int* __restrict__ amask,
             float* __restrict__ out,
             float* __restrict__ mask_out) {
    int lid = blockIdx.x;
    int b = lid & (BATCH - 1);   // fast axis
    int w = lid >> 8;            // slow axis
    int t = threadIdx.x;         // 0..63

    __shared__ int ssum[2];
    __shared__ int slast;

    // --- metadata: 2KB word row + 2KB mask row, cooperative, L2-cached ---
    const int4* wp = reinterpret_cast<const int4*>(word_ids + b * LSEQ);
    int4 w0 = __ldg(wp + 2 * t);
    int4 w1 = __ldg(wp + 2 * t + 1);
    const int4* mp = reinterpret_cast<const int4*>(amask + b * LSEQ);
    int4 m0 = __ldg(mp + 2 * t);
    int4 m1 = __ldg(mp + 2 * t + 1);

    int ids[8] = { clampw(w0.x), clampw(w0.y), clampw(w0.z), clampw(w0.w),
                   clampw(w1.x), clampw(w1.y), clampw(w1.z), clampw(w1.w) };

    int cw = 0, ce = 0;
    #pragma unroll
    for (int i = 0; i < 8; ++i) {
        cw += (ids[i] < w);
        ce += (ids[i] <= w);
    }
    int msum = m0.x + m0.y + m0.z + m0.w + m1.x + m1.y + m1.z + m1.w;

    // pack three partials (each <= 512) into one int: 10|10|12 bits
    int packed = cw | (ce << 10) | (msum << 20);
    #pragma unroll
    for (int sft = 16; sft > 0; sft >>= 1)
        packed += __shfl_down_sync(0xffffffffu, packed, sft);
    if ((t & 31) == 0) ssum[t >> 5] = packed;
    if (t == 63) slast = ids[7];
    __syncthreads();

    int tot = ssum[0] + ssum[1];
    int s  = tot & 1023;
    int e  = (tot >> 10) & 1023;
    int hi = (tot >> 20) - 1;          // 1 + (sum(mask) - 2)
    int wordnum = slast + 1;           // sorted -> last id is max

    s = s > 1 ? s : 1;
    e = e < hi ? e : hi;
    int n = e - s;                     // may be <= 0 (empty / padded word)

    // --- pooling ---
    const int stride4 = BATCH * DDIM / 4;
    const float4* p = reinterpret_cast<const float4*>(cf)
                    + (long long)s * stride4 + b * (DDIM / 4) + t;

    float4 acc = pool_body(p, stride4, n);

    float inv = 1.0f / (float)(n > 0 ? n : 1);
    acc.x *= inv; acc.y *= inv; acc.z *= inv; acc.w *= inv;

    float4* o = reinterpret_cast<float4*>(out)
              + (long long)(w * BATCH + b) * (DDIM / 4) + t;
    __stcs(o, acc);

    if (t == 0 && mask_out != nullptr) {
        __stcs(&mask_out[w * BATCH + b], (w < wordnum) ? 1.0f : 0.0f);
    }
}

extern "C" void kernel_launch(void* const* d_in, const int* in_sizes, int n_in,
                              void* d_out, int out_size) {
    const float* char_feats = (const float*)d_in[0];
    const int*   word_ids   = (const int*)d_in[1];
    const int*   amask      = (const int*)d_in[2];
    float* out = (float*)d_out;

    const int feats_elems = NW * BATCH * DDIM;
    float* mask_out = (out_size > feats_elems) ? (out + feats_elems) : nullptr;

    fused_kernel<<<NW * BATCH, 64>>>(char_feats, word_ids, amask, out, mask_out);
}